// round 1
// baseline (speedup 1.0000x reference)
#include <cuda_runtime.h>
#include <math.h>

#define BB 2
#define SS 2048
#define HH 1024
#define NHEADS 16
#define HDIM 64
#define MTOT (BB*SS)      // 4096
#define NQKV (3*HH)       // 3072

// Scratch (allocation-free rule: __device__ globals)
__device__ float g_qkv[(size_t)MTOT * NQKV];  // 48 MiB
__device__ float g_ctx[(size_t)MTOT * HH];    // 16 MiB
__device__ float g_x[(size_t)MTOT * HH];      // 16 MiB

// ---------------------------------------------------------------------------
// Classic SGEMM: C[M,N] = A[M,K] @ B[K,N] + bias[N] (+ res[M,N] if RES)
// 128x128 tile, BK=8, 256 threads, 8x8 per thread.
// ---------------------------------------------------------------------------
template<bool RES>
__global__ __launch_bounds__(256)
void sgemm_kernel(const float* __restrict__ A, const float* __restrict__ Bm,
                  const float* __restrict__ bias, const float* __restrict__ res,
                  float* __restrict__ C, int M, int N, int K)
{
    __shared__ float As[8][128];
    __shared__ float Bs[8][128];

    const int tid = threadIdx.x;
    const int bm = blockIdx.y * 128;
    const int bn = blockIdx.x * 128;
    const int ty = tid >> 4;       // 0..15
    const int tx = tid & 15;       // 0..15

    const int arow = tid >> 1;           // 0..127
    const int acol = (tid & 1) * 4;      // 0 or 4
    const int brow = tid >> 5;           // 0..7
    const int bcol = (tid & 31) * 4;     // 0..124

    const float* Aptr = A + (size_t)(bm + arow) * K + acol;
    const float* Bptr = Bm + (size_t)brow * N + bn + bcol;

    float acc[8][8];
#pragma unroll
    for (int i = 0; i < 8; i++)
#pragma unroll
        for (int j = 0; j < 8; j++) acc[i][j] = 0.0f;

    for (int k0 = 0; k0 < K; k0 += 8) {
        float4 av = *(const float4*)(Aptr + k0);
        float4 bv = *(const float4*)(Bptr + (size_t)k0 * N);
        As[acol + 0][arow] = av.x;
        As[acol + 1][arow] = av.y;
        As[acol + 2][arow] = av.z;
        As[acol + 3][arow] = av.w;
        *(float4*)&Bs[brow][bcol] = bv;
        __syncthreads();

#pragma unroll
        for (int kk = 0; kk < 8; kk++) {
            float ra[8], rb[8];
            *(float4*)(ra)     = *(const float4*)&As[kk][ty * 8];
            *(float4*)(ra + 4) = *(const float4*)&As[kk][ty * 8 + 4];
            *(float4*)(rb)     = *(const float4*)&Bs[kk][tx * 8];
            *(float4*)(rb + 4) = *(const float4*)&Bs[kk][tx * 8 + 4];
#pragma unroll
            for (int i = 0; i < 8; i++)
#pragma unroll
                for (int j = 0; j < 8; j++)
                    acc[i][j] += ra[i] * rb[j];
        }
        __syncthreads();
    }

#pragma unroll
    for (int i = 0; i < 8; i++) {
        int r = bm + ty * 8 + i;
#pragma unroll
        for (int j = 0; j < 8; j += 4) {
            int c = bn + tx * 8 + j;
            float4 o;
            o.x = acc[i][j + 0] + bias[c + 0];
            o.y = acc[i][j + 1] + bias[c + 1];
            o.z = acc[i][j + 2] + bias[c + 2];
            o.w = acc[i][j + 3] + bias[c + 3];
            if (RES) {
                const float4 rv = *(const float4*)(res + (size_t)r * N + c);
                o.x += rv.x; o.y += rv.y; o.z += rv.z; o.w += rv.w;
            }
            *(float4*)(C + (size_t)r * N + c) = o;
        }
    }
}

// ---------------------------------------------------------------------------
// Flash-attention (fp32, online softmax). One block = one (batch,head) x 64
// query rows. Loops over 32 K/V tiles of 64 rows.
// qkv layout: [B*S, 3072], col = h*192 + {0:q, 64:k, 128:v} + d
// ---------------------------------------------------------------------------
__global__ __launch_bounds__(256)
void flash_attn_kernel(const float* __restrict__ qkv, float* __restrict__ ctx)
{
    extern __shared__ float sm[];
    // layouts: Qs[d][qr] (pad 68), Ks[d][kk] (pad 68), Vs[kk][d] (pad 68),
    //          Ps[qr][kk] (pad 65), Lp[4][64]
    float (*Qs)[68] = (float(*)[68])(sm);
    float (*Ks)[68] = (float(*)[68])(sm + 64 * 68);
    float (*Vs)[68] = (float(*)[68])(sm + 2 * 64 * 68);
    float (*Ps)[65] = (float(*)[65])(sm + 3 * 64 * 68);
    float (*Lp)[64] = (float(*)[64])(sm + 3 * 64 * 68 + 64 * 65);

    const int bh = blockIdx.x;            // 0..31
    const int qt = blockIdx.y;            // 0..31
    const int b  = bh >> 4;
    const int h  = bh & 15;
    const float* base = qkv + (size_t)b * SS * NQKV + h * (3 * HDIM);

    const int tid = threadIdx.x;
    const float scale = 0.125f;           // 1/sqrt(64)

    // Load Q tile transposed (scaled)
#pragma unroll
    for (int it = 0; it < 4; it++) {
        int L  = it * 256 + tid;
        int qr = L >> 4;
        int d4 = (L & 15) * 4;
        float4 v = *(const float4*)(base + (size_t)(qt * 64 + qr) * NQKV + d4);
        Qs[d4 + 0][qr] = v.x * scale;
        Qs[d4 + 1][qr] = v.y * scale;
        Qs[d4 + 2][qr] = v.z * scale;
        Qs[d4 + 3][qr] = v.w * scale;
    }

    const int si = tid >> 4;     // S-compute q group (0..15)
    const int sj = tid & 15;     // S-compute k group (0..15)
    const int qr = tid & 63;     // row ownership
    const int dg = tid >> 6;     // d quarter (0..3)

    float m = -1e30f;
    float lpart = 0.0f;
    float oacc[16];
#pragma unroll
    for (int t = 0; t < 16; t++) oacc[t] = 0.0f;

    for (int kt = 0; kt < 32; kt++) {
        __syncthreads();  // prev PV done (and Q visible on first iter)

        // Load K (transposed) and V (natural)
#pragma unroll
        for (int it = 0; it < 4; it++) {
            int L  = it * 256 + tid;
            int kk = L >> 4;
            int d4 = (L & 15) * 4;
            const float* rp = base + (size_t)(kt * 64 + kk) * NQKV + d4;
            float4 kv = *(const float4*)(rp + HDIM);
            Ks[d4 + 0][kk] = kv.x;
            Ks[d4 + 1][kk] = kv.y;
            Ks[d4 + 2][kk] = kv.z;
            Ks[d4 + 3][kk] = kv.w;
            float4 vv = *(const float4*)(rp + 2 * HDIM);
            *(float4*)&Vs[kk][d4] = vv;
        }
        __syncthreads();

        // S = Q K^T (scaled). Each thread: 4x4 sub-block.
        float sreg[16];
#pragma unroll
        for (int t = 0; t < 16; t++) sreg[t] = 0.0f;
#pragma unroll 8
        for (int d = 0; d < 64; d++) {
            float4 aq = *(const float4*)&Qs[d][si * 4];
            float4 bk = *(const float4*)&Ks[d][sj * 4];
            sreg[0]  += aq.x * bk.x;  sreg[1]  += aq.x * bk.y;
            sreg[2]  += aq.x * bk.z;  sreg[3]  += aq.x * bk.w;
            sreg[4]  += aq.y * bk.x;  sreg[5]  += aq.y * bk.y;
            sreg[6]  += aq.y * bk.z;  sreg[7]  += aq.y * bk.w;
            sreg[8]  += aq.z * bk.x;  sreg[9]  += aq.z * bk.y;
            sreg[10] += aq.z * bk.z;  sreg[11] += aq.z * bk.w;
            sreg[12] += aq.w * bk.x;  sreg[13] += aq.w * bk.y;
            sreg[14] += aq.w * bk.z;  sreg[15] += aq.w * bk.w;
        }
#pragma unroll
        for (int r = 0; r < 4; r++)
#pragma unroll
            for (int c = 0; c < 4; c++)
                Ps[si * 4 + r][sj * 4 + c] = sreg[r * 4 + c];
        __syncthreads();

        // Row stats (each of 4 owning threads scans full row redundantly)
        float tmax = -1e30f;
#pragma unroll 8
        for (int kk = 0; kk < 64; kk++)
            tmax = fmaxf(tmax, Ps[qr][kk]);
        float mnew  = fmaxf(m, tmax);
        float alpha = __expf(m - mnew);
        __syncthreads();  // all raw reads done before exp overwrite

        float psum = 0.0f;
#pragma unroll
        for (int t = 0; t < 16; t++) {
            int kk = dg * 16 + t;
            float e = __expf(Ps[qr][kk] - mnew);
            Ps[qr][kk] = e;
            psum += e;
        }
        lpart = lpart * alpha + psum;
#pragma unroll
        for (int t = 0; t < 16; t++) oacc[t] *= alpha;
        m = mnew;
        __syncthreads();

        // PV accumulate: this thread's 16 d-columns
#pragma unroll 4
        for (int kk = 0; kk < 64; kk++) {
            float p = Ps[qr][kk];
            const float4* vp = (const float4*)&Vs[kk][dg * 16];
            float4 v0 = vp[0], v1 = vp[1], v2 = vp[2], v3 = vp[3];
            oacc[0]  += p * v0.x;  oacc[1]  += p * v0.y;
            oacc[2]  += p * v0.z;  oacc[3]  += p * v0.w;
            oacc[4]  += p * v1.x;  oacc[5]  += p * v1.y;
            oacc[6]  += p * v1.z;  oacc[7]  += p * v1.w;
            oacc[8]  += p * v2.x;  oacc[9]  += p * v2.y;
            oacc[10] += p * v2.z;  oacc[11] += p * v2.w;
            oacc[12] += p * v3.x;  oacc[13] += p * v3.y;
            oacc[14] += p * v3.z;  oacc[15] += p * v3.w;
        }
    }

    __syncthreads();
    Lp[dg][qr] = lpart;
    __syncthreads();
    float l = Lp[0][qr] + Lp[1][qr] + Lp[2][qr] + Lp[3][qr];
    float inv = 1.0f / l;

    float* op = ctx + (size_t)(b * SS + qt * 64 + qr) * HH + h * HDIM + dg * 16;
#pragma unroll
    for (int t = 0; t < 16; t += 4) {
        float4 o;
        o.x = oacc[t + 0] * inv;
        o.y = oacc[t + 1] * inv;
        o.z = oacc[t + 2] * inv;
        o.w = oacc[t + 3] * inv;
        *(float4*)(op + t) = o;
    }
}

// ---------------------------------------------------------------------------
// LayerNorm over H=1024, one block per row, residual already in x.
// ---------------------------------------------------------------------------
__global__ __launch_bounds__(256)
void layernorm_kernel(const float* __restrict__ x, const float* __restrict__ gamma,
                      const float* __restrict__ beta, float* __restrict__ out)
{
    __shared__ float red[256];
    const int row = blockIdx.x;
    const int tid = threadIdx.x;

    const float4 v = ((const float4*)(x + (size_t)row * HH))[tid];
    float s = v.x + v.y + v.z + v.w;
    red[tid] = s;
    __syncthreads();
#pragma unroll
    for (int o = 128; o > 0; o >>= 1) {
        if (tid < o) red[tid] += red[tid + o];
        __syncthreads();
    }
    const float mu = red[0] * (1.0f / HH);
    __syncthreads();

    const float dx = v.x - mu, dy = v.y - mu, dz = v.z - mu, dw = v.w - mu;
    red[tid] = dx * dx + dy * dy + dz * dz + dw * dw;
    __syncthreads();
#pragma unroll
    for (int o = 128; o > 0; o >>= 1) {
        if (tid < o) red[tid] += red[tid + o];
        __syncthreads();
    }
    const float var = red[0] * (1.0f / HH);
    const float rstd = rsqrtf(var + 1e-5f);

    const float4 g  = ((const float4*)gamma)[tid];
    const float4 bt = ((const float4*)beta)[tid];
    float4 o;
    o.x = dx * rstd * g.x + bt.x;
    o.y = dy * rstd * g.y + bt.y;
    o.z = dz * rstd * g.z + bt.z;
    o.w = dw * rstd * g.w + bt.w;
    ((float4*)(out + (size_t)row * HH))[tid] = o;
}

// ---------------------------------------------------------------------------
extern "C" void kernel_launch(void* const* d_in, const int* in_sizes, int n_in,
                              void* d_out, int out_size)
{
    const float* hidden  = (const float*)d_in[0];
    const float* w_qkv   = (const float*)d_in[1];
    const float* b_qkv   = (const float*)d_in[2];
    const float* w_dense = (const float*)d_in[3];
    const float* b_dense = (const float*)d_in[4];
    const float* gamma   = (const float*)d_in[5];
    const float* beta    = (const float*)d_in[6];
    float* out = (float*)d_out;

    float *qkv, *ctx, *x;
    cudaGetSymbolAddress((void**)&qkv, g_qkv);
    cudaGetSymbolAddress((void**)&ctx, g_ctx);
    cudaGetSymbolAddress((void**)&x,   g_x);

    // 1) QKV projection
    sgemm_kernel<false><<<dim3(NQKV / 128, MTOT / 128), 256>>>(
        hidden, w_qkv, b_qkv, nullptr, qkv, MTOT, NQKV, HH);

    // 2) Attention
    const int smem = (3 * 64 * 68 + 64 * 65 + 4 * 64) * (int)sizeof(float); // 69888
    cudaFuncSetAttribute(flash_attn_kernel,
                         cudaFuncAttributeMaxDynamicSharedMemorySize, smem);
    flash_attn_kernel<<<dim3(32, 32), 256, smem>>>(qkv, ctx);

    // 3) Dense projection + bias + residual
    sgemm_kernel<true><<<dim3(HH / 128, MTOT / 128), 256>>>(
        ctx, w_dense, b_dense, hidden, x, MTOT, HH, HH);

    // 4) LayerNorm
    layernorm_kernel<<<MTOT, 256>>>(x, gamma, beta, out);
}

// round 3
// speedup vs baseline: 2.8399x; 2.8399x over previous
#include <cuda_runtime.h>
#include <cstdint>
#include <math.h>

#define BB 2
#define SS 2048
#define HH 1024
#define NHEADS 16
#define HDIM 64
#define MTOT (BB*SS)      // 4096
#define NQKV (3*HH)       // 3072

// Scratch (allocation-free rule: __device__ globals)
__device__ float g_qkv[(size_t)MTOT * NQKV];      // 48 MiB (rounded, Q pre-scaled)
__device__ float g_ctx[(size_t)MTOT * HH];        // 16 MiB (rounded)
__device__ float g_x[(size_t)MTOT * HH];          // 16 MiB
__device__ float g_hid_rna[(size_t)MTOT * HH];    // 16 MiB
__device__ float g_wqkv_rna[(size_t)HH * NQKV];   // 12 MiB
__device__ float g_wdense_rna[(size_t)HH * HH];   // 4 MiB

// ============================================================================
// helpers
// ============================================================================
__device__ __forceinline__ uint32_t smem_u32(const void* p) {
    uint32_t a;
    asm("{ .reg .u64 t; cvta.to.shared.u64 t, %1; cvt.u32.u64 %0, t; }"
        : "=r"(a) : "l"(p));
    return a;
}
__device__ __forceinline__ float rna_tf32(float x) {
    uint32_t u; asm("cvt.rna.tf32.f32 %0, %1;" : "=r"(u) : "f"(x));
    return __uint_as_float(u);
}
__device__ __forceinline__ void cpasync16(uint32_t s, const void* g) {
    asm volatile("cp.async.cg.shared.global [%0], [%1], 16;" :: "r"(s), "l"(g));
}
#define CP_COMMIT() asm volatile("cp.async.commit_group;" ::: "memory")
#define CP_WAIT0()  asm volatile("cp.async.wait_group 0;" ::: "memory")
#define CP_WAIT1()  asm volatile("cp.async.wait_group 1;" ::: "memory")

// m16n8k8 tf32 MMA (sm_80+ baseline PTX — legal on sm_103 target)
__device__ __forceinline__ void mma_tf32(float c[4], const uint32_t a[4],
                                         const uint32_t b[2]) {
    asm volatile(
        "mma.sync.aligned.m16n8k8.row.col.f32.tf32.tf32.f32 "
        "{%0,%1,%2,%3}, {%4,%5,%6,%7}, {%8,%9}, {%0,%1,%2,%3};\n"
        : "+f"(c[0]), "+f"(c[1]), "+f"(c[2]), "+f"(c[3])
        : "r"(a[0]), "r"(a[1]), "r"(a[2]), "r"(a[3]), "r"(b[0]), "r"(b[1]));
}
#define F2U(x) __float_as_uint(x)

// ============================================================================
// prep: tf32 round-to-nearest copy
// ============================================================================
__global__ __launch_bounds__(256)
void rna_copy_kernel(const float* __restrict__ in, float* __restrict__ out) {
    size_t i = (size_t)blockIdx.x * 256 + threadIdx.x;
    float4 v = ((const float4*)in)[i];
    v.x = rna_tf32(v.x); v.y = rna_tf32(v.y);
    v.z = rna_tf32(v.z); v.w = rna_tf32(v.w);
    ((float4*)out)[i] = v;
}

// ============================================================================
// tf32 MMA GEMM: C[M,N] = A[M,K] @ B[K,N] + bias (+res | +qkv-postproc)
// 128x128 CTA tile, BK=32, 256 threads (8 warps, 32x64 warp tiles),
// cp.async double buffer. A,B must be tf32-pre-rounded.
// QKVPOST: round output to tf32 and scale Q columns (c%192<64) by 0.125.
// ============================================================================
#define AS_STRIDE 36
#define BS_STRIDE 136
#define AS_FLOATS (128 * AS_STRIDE)   // 4608 per stage
#define BS_FLOATS (32 * BS_STRIDE)    // 4352 per stage
#define GEMM_SMEM_FLOATS (2 * AS_FLOATS + 2 * BS_FLOATS)  // 17920
#define GEMM_SMEM_BYTES  (GEMM_SMEM_FLOATS * 4)           // 71680

template<bool RES, bool QKVPOST>
__global__ __launch_bounds__(256)
void gemm_mma_kernel(const float* __restrict__ A, const float* __restrict__ B,
                     const float* __restrict__ bias, const float* __restrict__ res,
                     float* __restrict__ C, int K, int N)
{
    extern __shared__ float sh[];
    float* As = sh;                       // [2][128][36]
    float* Bs = sh + 2 * AS_FLOATS;       // [2][32][136]

    const int tid = threadIdx.x;
    const int w = tid >> 5, lane = tid & 31;
    const int g = lane >> 2, tig = lane & 3;
    const int wm = w >> 1, wn = w & 1;
    const int bm = blockIdx.y * 128, bn = blockIdx.x * 128;
    const int nst = K / 32;

    float cf[2][8][4];
#pragma unroll
    for (int mi = 0; mi < 2; mi++)
#pragma unroll
        for (int ni = 0; ni < 8; ni++)
#pragma unroll
            for (int q = 0; q < 4; q++) cf[mi][ni][q] = 0.0f;

    auto load_stage = [&](int buf, int ks) {
#pragma unroll
        for (int i = 0; i < 4; i++) {
            int l = tid + i * 256;
            int row = l >> 3, seg = l & 7;
            cpasync16(smem_u32(As + buf * AS_FLOATS + row * AS_STRIDE + seg * 4),
                      A + (size_t)(bm + row) * K + ks * 32 + seg * 4);
        }
#pragma unroll
        for (int i = 0; i < 4; i++) {
            int l = tid + i * 256;
            int kr = l >> 5, seg = l & 31;
            cpasync16(smem_u32(Bs + buf * BS_FLOATS + kr * BS_STRIDE + seg * 4),
                      B + (size_t)(ks * 32 + kr) * N + bn + seg * 4);
        }
    };

    load_stage(0, 0); CP_COMMIT();
    load_stage(1, 1); CP_COMMIT();

    for (int ks = 0; ks < nst; ks++) {
        const int buf = ks & 1;
        if (ks == nst - 1) { CP_WAIT0(); } else { CP_WAIT1(); }
        __syncthreads();

        const float* Ab = As + buf * AS_FLOATS;
        const float* Bb = Bs + buf * BS_FLOATS;
#pragma unroll
        for (int kc = 0; kc < 4; kc++) {
            uint32_t af[2][4];
#pragma unroll
            for (int mi = 0; mi < 2; mi++) {
                const float* ap = Ab + (wm * 32 + mi * 16 + g) * AS_STRIDE + kc * 8 + tig;
                af[mi][0] = F2U(ap[0]);
                af[mi][1] = F2U(ap[8 * AS_STRIDE]);
                af[mi][2] = F2U(ap[4]);
                af[mi][3] = F2U(ap[8 * AS_STRIDE + 4]);
            }
            uint32_t bf[8][2];
#pragma unroll
            for (int ni = 0; ni < 8; ni++) {
                const float* bp = Bb + (kc * 8 + tig) * BS_STRIDE + wn * 64 + ni * 8 + g;
                bf[ni][0] = F2U(bp[0]);
                bf[ni][1] = F2U(bp[4 * BS_STRIDE]);
            }
#pragma unroll
            for (int mi = 0; mi < 2; mi++)
#pragma unroll
                for (int ni = 0; ni < 8; ni++)
                    mma_tf32(cf[mi][ni], af[mi], bf[ni]);
        }
        __syncthreads();
        if (ks + 2 < nst) { load_stage(buf, ks + 2); CP_COMMIT(); }
    }

    // epilogue
#pragma unroll
    for (int mi = 0; mi < 2; mi++) {
        const int r = bm + wm * 32 + mi * 16 + g;
#pragma unroll
        for (int ni = 0; ni < 8; ni++) {
            const int c = bn + wn * 64 + ni * 8 + 2 * tig;
            float v0 = cf[mi][ni][0] + bias[c];
            float v1 = cf[mi][ni][1] + bias[c + 1];
            float v2 = cf[mi][ni][2] + bias[c];
            float v3 = cf[mi][ni][3] + bias[c + 1];
            if (RES) {
                const float2 r0 = *(const float2*)(res + (size_t)r * N + c);
                const float2 r1 = *(const float2*)(res + (size_t)(r + 8) * N + c);
                v0 += r0.x; v1 += r0.y; v2 += r1.x; v3 += r1.y;
            }
            if (QKVPOST) {
                if ((c % 192) < 64) { v0 *= 0.125f; v1 *= 0.125f; v2 *= 0.125f; v3 *= 0.125f; }
                v0 = rna_tf32(v0); v1 = rna_tf32(v1);
                v2 = rna_tf32(v2); v3 = rna_tf32(v3);
            }
            *(float2*)(C + (size_t)r * N + c) = make_float2(v0, v1);
            *(float2*)(C + (size_t)(r + 8) * N + c) = make_float2(v2, v3);
        }
    }
}

// ============================================================================
// Flash attention with tf32 MMA for S=QK^T and O+=PV.
// Block: 256 thr (8 warps), 64 q-rows, loops 32 k-tiles of 64.
// qkv is tf32-rounded and Q pre-scaled by 1/8 (done in QKV GEMM epilogue).
// ============================================================================
#define QS_STRIDE 68
#define KS_STRIDE 72
#define PS_STRIDE 66
#define OFF_Q 0
#define OFF_K (64 * QS_STRIDE)                    // 4352
#define OFF_V (OFF_K + 2 * 64 * KS_STRIDE)        // 13568
#define OFF_P (OFF_V + 2 * 64 * KS_STRIDE)        // 22784
#define OFF_M (OFF_P + 64 * PS_STRIDE)            // 27008 ([4][64])
#define OFF_AL (OFF_M + 256)                      // 27264 ([64])
#define ATTN_SMEM_FLOATS (OFF_AL + 64)            // 27328
#define ATTN_SMEM_BYTES (ATTN_SMEM_FLOATS * 4)    // 109312

__global__ __launch_bounds__(256)
void attn_mma_kernel(const float* __restrict__ qkv, float* __restrict__ ctx)
{
    extern __shared__ float sh[];
    float* Qs = sh + OFF_Q;   // [64][68]
    float* Ks = sh + OFF_K;   // [2][64][72]
    float* Vs = sh + OFF_V;   // [2][64][72]
    float* Ps = sh + OFF_P;   // [64][66]
    float* Mp = sh + OFF_M;   // [4][64]
    float* Al = sh + OFF_AL;  // [64]

    const int bh = blockIdx.x, qt = blockIdx.y;
    const int b = bh >> 4, h = bh & 15;
    const float* base = qkv + (size_t)b * SS * NQKV + h * (3 * HDIM);

    const int tid = threadIdx.x;
    const int w = tid >> 5, lane = tid & 31;
    const int g = lane >> 2, tig = lane & 3;
    const int wm = w >> 1, wn = w & 1;
    const int r0 = wm * 16, cw = wn * 32;
    const int qr = tid & 63, dg = tid >> 6;

    // Q tile load (rows qt*64+.., cols h*192+0..63)
#pragma unroll
    for (int i = 0; i < 4; i++) {
        int l = tid + i * 256;
        int row = l >> 4, seg = l & 15;
        cpasync16(smem_u32(Qs + row * QS_STRIDE + seg * 4),
                  base + (size_t)(qt * 64 + row) * NQKV + seg * 4);
    }
    auto load_kv = [&](int kt, int buf) {
#pragma unroll
        for (int i = 0; i < 4; i++) {
            int l = tid + i * 256;
            int row = l >> 4, seg = l & 15;
            const float* gp = base + (size_t)(kt * 64 + row) * NQKV + HDIM + seg * 4;
            cpasync16(smem_u32(Ks + buf * (64 * KS_STRIDE) + row * KS_STRIDE + seg * 4), gp);
            cpasync16(smem_u32(Vs + buf * (64 * KS_STRIDE) + row * KS_STRIDE + seg * 4), gp + HDIM);
        }
    };
    load_kv(0, 0);
    CP_COMMIT();

    float m = -1e30f, lp = 0.0f;
    float o[4][4];
#pragma unroll
    for (int ni = 0; ni < 4; ni++)
#pragma unroll
        for (int q = 0; q < 4; q++) o[ni][q] = 0.0f;

    for (int kt = 0; kt < 32; kt++) {
        const int buf = kt & 1;
        if (kt + 1 < 32) { load_kv(kt + 1, buf ^ 1); CP_COMMIT(); CP_WAIT1(); }
        else { CP_WAIT0(); }
        __syncthreads();

        // ---- S = Q K^T (tf32 mma) ----
        const float* Kb = Ks + buf * (64 * KS_STRIDE);
        float sfr[4][4];
#pragma unroll
        for (int ni = 0; ni < 4; ni++)
#pragma unroll
            for (int q = 0; q < 4; q++) sfr[ni][q] = 0.0f;
#pragma unroll
        for (int kc = 0; kc < 8; kc++) {
            uint32_t af[4];
            const float* ap = Qs + (r0 + g) * QS_STRIDE + kc * 8 + tig;
            af[0] = F2U(ap[0]);
            af[1] = F2U(ap[8 * QS_STRIDE]);
            af[2] = F2U(ap[4]);
            af[3] = F2U(ap[8 * QS_STRIDE + 4]);
            uint32_t bf[2];
#pragma unroll
            for (int ni = 0; ni < 4; ni++) {
                const float* bp = Kb + (cw + ni * 8 + g) * KS_STRIDE + kc * 8 + tig;
                bf[0] = F2U(bp[0]);
                bf[1] = F2U(bp[4]);
                mma_tf32(sfr[ni], af, bf);
            }
        }
#pragma unroll
        for (int ni = 0; ni < 4; ni++) {
            int c = cw + ni * 8 + 2 * tig;
            *(float2*)(Ps + (r0 + g) * PS_STRIDE + c) = make_float2(sfr[ni][0], sfr[ni][1]);
            *(float2*)(Ps + (r0 + g + 8) * PS_STRIDE + c) = make_float2(sfr[ni][2], sfr[ni][3]);
        }
        __syncthreads();

        // ---- online softmax (thread (qr,dg) owns 16 cols of row qr) ----
        float tmax = -1e30f;
#pragma unroll
        for (int t = 0; t < 16; t++)
            tmax = fmaxf(tmax, Ps[qr * PS_STRIDE + dg * 16 + t]);
        Mp[dg * 64 + qr] = tmax;
        __syncthreads();

        float mnew = fmaxf(fmaxf(Mp[qr], Mp[64 + qr]), fmaxf(Mp[128 + qr], Mp[192 + qr]));
        mnew = fmaxf(m, mnew);
        float alpha = __expf(m - mnew);
        float ps = 0.0f;
#pragma unroll
        for (int t = 0; t < 16; t++) {
            int idx = qr * PS_STRIDE + dg * 16 + t;
            float e = __expf(Ps[idx] - mnew);
            ps += e;
            Ps[idx] = rna_tf32(e);
        }
        lp = lp * alpha + ps;
        m = mnew;
        if (dg == 0) Al[qr] = alpha;
        __syncthreads();

        // ---- O = O*alpha + P V (tf32 mma) ----
        const float a0 = Al[r0 + g], a1 = Al[r0 + g + 8];
#pragma unroll
        for (int ni = 0; ni < 4; ni++) {
            o[ni][0] *= a0; o[ni][1] *= a0;
            o[ni][2] *= a1; o[ni][3] *= a1;
        }
        const float* Vb = Vs + buf * (64 * KS_STRIDE);
#pragma unroll
        for (int kc = 0; kc < 8; kc++) {
            uint32_t af[4];
            const float* ap = Ps + (r0 + g) * PS_STRIDE + kc * 8 + tig;
            af[0] = F2U(ap[0]);
            af[1] = F2U(ap[8 * PS_STRIDE]);
            af[2] = F2U(ap[4]);
            af[3] = F2U(ap[8 * PS_STRIDE + 4]);
            uint32_t bf[2];
#pragma unroll
            for (int ni = 0; ni < 4; ni++) {
                const float* bp = Vb + (kc * 8 + tig) * KS_STRIDE + cw + ni * 8 + g;
                bf[0] = F2U(bp[0]);
                bf[1] = F2U(bp[4 * KS_STRIDE]);
                mma_tf32(o[ni], af, bf);
            }
        }
        __syncthreads();
    }

    // ---- finalize: divide by l, store ctx (tf32-rounded for dense GEMM) ----
    Mp[dg * 64 + qr] = lp;
    __syncthreads();
    const int rr0 = r0 + g, rr1 = r0 + g + 8;
    float l0 = Mp[rr0] + Mp[64 + rr0] + Mp[128 + rr0] + Mp[192 + rr0];
    float l1 = Mp[rr1] + Mp[64 + rr1] + Mp[128 + rr1] + Mp[192 + rr1];
    float i0 = 1.0f / l0, i1 = 1.0f / l1;

    const size_t grow0 = (size_t)(b * SS + qt * 64 + rr0) * HH;
    const size_t grow1 = (size_t)(b * SS + qt * 64 + rr1) * HH;
#pragma unroll
    for (int ni = 0; ni < 4; ni++) {
        int col = h * HDIM + cw + ni * 8 + 2 * tig;
        *(float2*)(ctx + grow0 + col) =
            make_float2(rna_tf32(o[ni][0] * i0), rna_tf32(o[ni][1] * i0));
        *(float2*)(ctx + grow1 + col) =
            make_float2(rna_tf32(o[ni][2] * i1), rna_tf32(o[ni][3] * i1));
    }
}

// ============================================================================
// LayerNorm over H=1024, one block per row.
// ============================================================================
__global__ __launch_bounds__(256)
void layernorm_kernel(const float* __restrict__ x, const float* __restrict__ gamma,
                      const float* __restrict__ beta, float* __restrict__ out)
{
    __shared__ float red[256];
    const int row = blockIdx.x;
    const int tid = threadIdx.x;

    const float4 v = ((const float4*)(x + (size_t)row * HH))[tid];
    float s = v.x + v.y + v.z + v.w;
    red[tid] = s;
    __syncthreads();
#pragma unroll
    for (int o = 128; o > 0; o >>= 1) {
        if (tid < o) red[tid] += red[tid + o];
        __syncthreads();
    }
    const float mu = red[0] * (1.0f / HH);
    __syncthreads();

    const float dx = v.x - mu, dy = v.y - mu, dz = v.z - mu, dw = v.w - mu;
    red[tid] = dx * dx + dy * dy + dz * dz + dw * dw;
    __syncthreads();
#pragma unroll
    for (int o = 128; o > 0; o >>= 1) {
        if (tid < o) red[tid] += red[tid + o];
        __syncthreads();
    }
    const float var = red[0] * (1.0f / HH);
    const float rstd = rsqrtf(var + 1e-5f);

    const float4 gm = ((const float4*)gamma)[tid];
    const float4 bt = ((const float4*)beta)[tid];
    float4 o;
    o.x = dx * rstd * gm.x + bt.x;
    o.y = dy * rstd * gm.y + bt.y;
    o.z = dz * rstd * gm.z + bt.z;
    o.w = dw * rstd * gm.w + bt.w;
    ((float4*)(out + (size_t)row * HH))[tid] = o;
}

// ============================================================================
extern "C" void kernel_launch(void* const* d_in, const int* in_sizes, int n_in,
                              void* d_out, int out_size)
{
    const float* hidden  = (const float*)d_in[0];
    const float* w_qkv   = (const float*)d_in[1];
    const float* b_qkv   = (const float*)d_in[2];
    const float* w_dense = (const float*)d_in[3];
    const float* b_dense = (const float*)d_in[4];
    const float* gamma   = (const float*)d_in[5];
    const float* beta    = (const float*)d_in[6];
    float* out = (float*)d_out;

    float *qkv, *ctx, *x, *hid, *wq, *wd;
    cudaGetSymbolAddress((void**)&qkv, g_qkv);
    cudaGetSymbolAddress((void**)&ctx, g_ctx);
    cudaGetSymbolAddress((void**)&x,   g_x);
    cudaGetSymbolAddress((void**)&hid, g_hid_rna);
    cudaGetSymbolAddress((void**)&wq,  g_wqkv_rna);
    cudaGetSymbolAddress((void**)&wd,  g_wdense_rna);

    // 0) tf32-round inputs once
    rna_copy_kernel<<<(MTOT * HH) / 1024, 256>>>(hidden, hid);
    rna_copy_kernel<<<(HH * NQKV) / 1024, 256>>>(w_qkv, wq);
    rna_copy_kernel<<<(HH * HH) / 1024, 256>>>(w_dense, wd);

    // 1) QKV projection (tensor cores); epilogue: +bias, Q*0.125, tf32 round
    cudaFuncSetAttribute(gemm_mma_kernel<false, true>,
                         cudaFuncAttributeMaxDynamicSharedMemorySize, GEMM_SMEM_BYTES);
    gemm_mma_kernel<false, true><<<dim3(NQKV / 128, MTOT / 128), 256, GEMM_SMEM_BYTES>>>(
        hid, wq, b_qkv, nullptr, qkv, HH, NQKV);

    // 2) Flash attention (tensor cores)
    cudaFuncSetAttribute(attn_mma_kernel,
                         cudaFuncAttributeMaxDynamicSharedMemorySize, ATTN_SMEM_BYTES);
    attn_mma_kernel<<<dim3(32, 32), 256, ATTN_SMEM_BYTES>>>(qkv, ctx);

    // 3) Dense projection + bias + residual (tensor cores)
    cudaFuncSetAttribute(gemm_mma_kernel<true, false>,
                         cudaFuncAttributeMaxDynamicSharedMemorySize, GEMM_SMEM_BYTES);
    gemm_mma_kernel<true, false><<<dim3(HH / 128, MTOT / 128), 256, GEMM_SMEM_BYTES>>>(
        ctx, wd, b_dense, hidden, x, HH, HH);

    // 4) LayerNorm
    layernorm_kernel<<<MTOT, 256>>>(x, gamma, beta, out);
}

// round 4
// speedup vs baseline: 6.6883x; 2.3551x over previous
#include <cuda_runtime.h>
#include <cuda_bf16.h>
#include <cstdint>
#include <math.h>

#define BB 2
#define SS 2048
#define HH 1024
#define NHEADS 16
#define HDIM 64
#define MTOT (BB*SS)      // 4096
#define NQKV (3*HH)       // 3072

// Scratch (allocation-free rule: __device__ globals)
__device__ __nv_bfloat16 g_hid_bf[(size_t)MTOT * HH];    // 8 MiB
__device__ __nv_bfloat16 g_wq_bf[(size_t)HH * NQKV];     // 6 MiB
__device__ __nv_bfloat16 g_wd_bf[(size_t)HH * HH];       // 2 MiB
__device__ __nv_bfloat16 g_qkv_bf[(size_t)MTOT * NQKV];  // 24 MiB (Q pre-scaled 1/8)
__device__ __nv_bfloat16 g_ctx_bf[(size_t)MTOT * HH];    // 8 MiB
__device__ float g_x[(size_t)MTOT * HH];                 // 16 MiB

// ============================================================================
// helpers
// ============================================================================
__device__ __forceinline__ uint32_t smem_u32(const void* p) {
    uint32_t a;
    asm("{ .reg .u64 t; cvta.to.shared.u64 t, %1; cvt.u32.u64 %0, t; }"
        : "=r"(a) : "l"(p));
    return a;
}
__device__ __forceinline__ void cpasync16(uint32_t s, const void* g) {
    asm volatile("cp.async.cg.shared.global [%0], [%1], 16;" :: "r"(s), "l"(g));
}
#define CP_COMMIT() asm volatile("cp.async.commit_group;" ::: "memory")
#define CP_WAIT0()  asm volatile("cp.async.wait_group 0;" ::: "memory")
#define CP_WAIT1()  asm volatile("cp.async.wait_group 1;" ::: "memory")

// pack two f32 -> bf16x2 (lo = first arg, hi = second arg)
__device__ __forceinline__ uint32_t pack_bf16(float lo, float hi) {
    uint32_t r;
    asm("cvt.rn.bf16x2.f32 %0, %1, %2;" : "=r"(r) : "f"(hi), "f"(lo));
    return r;
}

// m16n8k16 bf16 MMA, fp32 accumulate
__device__ __forceinline__ void mma_bf16(float c[4], const uint32_t a[4],
                                         const uint32_t b[2]) {
    asm volatile(
        "mma.sync.aligned.m16n8k16.row.col.f32.bf16.bf16.f32 "
        "{%0,%1,%2,%3}, {%4,%5,%6,%7}, {%8,%9}, {%0,%1,%2,%3};\n"
        : "+f"(c[0]), "+f"(c[1]), "+f"(c[2]), "+f"(c[3])
        : "r"(a[0]), "r"(a[1]), "r"(a[2]), "r"(a[3]), "r"(b[0]), "r"(b[1]));
}
__device__ __forceinline__ void ldmatrix_x4(uint32_t r[4], uint32_t addr) {
    asm volatile("ldmatrix.sync.aligned.m8n8.x4.shared.b16 {%0,%1,%2,%3}, [%4];"
                 : "=r"(r[0]), "=r"(r[1]), "=r"(r[2]), "=r"(r[3]) : "r"(addr));
}
__device__ __forceinline__ void ldmatrix_x4t(uint32_t r[4], uint32_t addr) {
    asm volatile("ldmatrix.sync.aligned.m8n8.x4.trans.shared.b16 {%0,%1,%2,%3}, [%4];"
                 : "=r"(r[0]), "=r"(r[1]), "=r"(r[2]), "=r"(r[3]) : "r"(addr));
}

// ============================================================================
// prep: fp32 -> bf16 convert
// ============================================================================
__global__ __launch_bounds__(256)
void f2bf_kernel(const float* __restrict__ in, __nv_bfloat16* __restrict__ out) {
    size_t i = (size_t)blockIdx.x * 256 + threadIdx.x;
    float4 v = ((const float4*)in)[i];
    uint2 o;
    o.x = pack_bf16(v.x, v.y);
    o.y = pack_bf16(v.z, v.w);
    ((uint2*)out)[i] = o;
}

// ============================================================================
// bf16 MMA GEMM: 128x128 CTA tile, BK=32, 256 threads (8 warps, 32x64 warp
// tiles), cp.async double buffer, ldmatrix fragments.
// QKV variant: out bf16, +bias, Q cols (c%192<64) scaled by 0.125.
// Dense variant: out fp32, +bias, +residual.
// ============================================================================
#define AS_STR 40
#define BS_STR 136
#define AS_ELE (128 * AS_STR)   // per stage (bf16)
#define BS_ELE (32 * BS_STR)
#define GEMM_SMEM_BYTES ((2 * AS_ELE + 2 * BS_ELE) * 2)   // 37888

template<bool QKV>
__global__ __launch_bounds__(256)
void gemm_bf16_kernel(const __nv_bfloat16* __restrict__ A,
                      const __nv_bfloat16* __restrict__ B,
                      const float* __restrict__ bias, const float* __restrict__ res,
                      void* __restrict__ Cout, int K, int N)
{
    extern __shared__ __align__(16) __nv_bfloat16 sh[];
    __nv_bfloat16* As = sh;                  // [2][128][40]
    __nv_bfloat16* Bs = sh + 2 * AS_ELE;     // [2][32][136]

    const int tid = threadIdx.x;
    const int w = tid >> 5, lane = tid & 31;
    const int g = lane >> 2, tig = lane & 3;
    const int wm = w >> 1, wn = w & 1;
    const int bm = blockIdx.y * 128, bn = blockIdx.x * 128;
    const int nst = K / 32;

    float cf[2][8][4];
#pragma unroll
    for (int mi = 0; mi < 2; mi++)
#pragma unroll
        for (int ni = 0; ni < 8; ni++)
#pragma unroll
            for (int q = 0; q < 4; q++) cf[mi][ni][q] = 0.0f;

    auto load_stage = [&](int buf, int ks) {
#pragma unroll
        for (int i = 0; i < 2; i++) {
            int l = tid + i * 256;
            int row = l >> 2, seg = l & 3;
            cpasync16(smem_u32(As + buf * AS_ELE + row * AS_STR + seg * 8),
                      A + (size_t)(bm + row) * K + ks * 32 + seg * 8);
        }
#pragma unroll
        for (int i = 0; i < 2; i++) {
            int l = tid + i * 256;
            int row = l >> 4, seg = l & 15;
            cpasync16(smem_u32(Bs + buf * BS_ELE + row * BS_STR + seg * 8),
                      B + (size_t)(ks * 32 + row) * N + bn + seg * 8);
        }
    };

    load_stage(0, 0); CP_COMMIT();
    load_stage(1, 1); CP_COMMIT();

    const int l16 = lane & 15;
    const int lhi = (lane >> 4) * 8;

    for (int ks = 0; ks < nst; ks++) {
        const int buf = ks & 1;
        if (ks == nst - 1) { CP_WAIT0(); } else { CP_WAIT1(); }
        __syncthreads();

        const __nv_bfloat16* Ab = As + buf * AS_ELE;
        const __nv_bfloat16* Bb = Bs + buf * BS_ELE;
#pragma unroll
        for (int kc = 0; kc < 2; kc++) {
            uint32_t au[2][4];
#pragma unroll
            for (int mi = 0; mi < 2; mi++)
                ldmatrix_x4(au[mi], smem_u32(Ab + (wm * 32 + mi * 16 + l16) * AS_STR
                                             + kc * 16 + lhi));
            uint32_t bu[8][2];
#pragma unroll
            for (int p = 0; p < 4; p++) {
                uint32_t t4[4];
                ldmatrix_x4t(t4, smem_u32(Bb + (kc * 16 + l16) * BS_STR
                                          + wn * 64 + p * 16 + lhi));
                bu[2 * p][0] = t4[0]; bu[2 * p][1] = t4[1];
                bu[2 * p + 1][0] = t4[2]; bu[2 * p + 1][1] = t4[3];
            }
#pragma unroll
            for (int mi = 0; mi < 2; mi++)
#pragma unroll
                for (int ni = 0; ni < 8; ni++)
                    mma_bf16(cf[mi][ni], au[mi], bu[ni]);
        }
        __syncthreads();
        if (ks + 2 < nst) { load_stage(buf, ks + 2); CP_COMMIT(); }
    }

    // epilogue
#pragma unroll
    for (int mi = 0; mi < 2; mi++) {
        const int r = bm + wm * 32 + mi * 16 + g;
#pragma unroll
        for (int ni = 0; ni < 8; ni++) {
            const int c = bn + wn * 64 + ni * 8 + 2 * tig;
            float v0 = cf[mi][ni][0] + bias[c];
            float v1 = cf[mi][ni][1] + bias[c + 1];
            float v2 = cf[mi][ni][2] + bias[c];
            float v3 = cf[mi][ni][3] + bias[c + 1];
            if (QKV) {
                if ((c % 192) < 64) { v0 *= 0.125f; v1 *= 0.125f; v2 *= 0.125f; v3 *= 0.125f; }
                __nv_bfloat16* Cb = (__nv_bfloat16*)Cout;
                *(uint32_t*)(Cb + (size_t)r * N + c) = pack_bf16(v0, v1);
                *(uint32_t*)(Cb + (size_t)(r + 8) * N + c) = pack_bf16(v2, v3);
            } else {
                float* Cf = (float*)Cout;
                const float2 r0 = *(const float2*)(res + (size_t)r * N + c);
                const float2 r1 = *(const float2*)(res + (size_t)(r + 8) * N + c);
                *(float2*)(Cf + (size_t)r * N + c) = make_float2(v0 + r0.x, v1 + r0.y);
                *(float2*)(Cf + (size_t)(r + 8) * N + c) = make_float2(v2 + r1.x, v3 + r1.y);
            }
        }
    }
}

// ============================================================================
// Flash attention, bf16 MMA, register-resident softmax.
// 256 threads / 8 warps; warp w owns q-rows w*16..w*16+15 of a 128-row tile,
// full n=64 per warp. 32 k-tiles of 64 keys, K/V double-buffered cp.async.
// ============================================================================
#define TS 72    // smem row stride in bf16 (144B, 16B-aligned, conflict-free)
#define ATTN_Q_ELE (128 * TS)
#define ATTN_KV_ELE (64 * TS)
#define ATTN_SMEM_BYTES ((ATTN_Q_ELE + 4 * ATTN_KV_ELE) * 2)  // 55296

__global__ __launch_bounds__(256)
void attn_bf16_kernel(const __nv_bfloat16* __restrict__ qkv,
                      __nv_bfloat16* __restrict__ ctx)
{
    extern __shared__ __align__(16) __nv_bfloat16 sha[];
    __nv_bfloat16* Qs = sha;                       // [128][72]
    __nv_bfloat16* Ks = sha + ATTN_Q_ELE;          // [2][64][72]
    __nv_bfloat16* Vs = Ks + 2 * ATTN_KV_ELE;      // [2][64][72]

    const int bh = blockIdx.x, qt = blockIdx.y;
    const int b = bh >> 4, h = bh & 15;
    const __nv_bfloat16* base = qkv + (size_t)b * SS * NQKV + h * (3 * HDIM);

    const int tid = threadIdx.x;
    const int w = tid >> 5, lane = tid & 31;
    const int g = lane >> 2, tig = lane & 3;
    const int l16 = lane & 15;
    const int lhi = (lane >> 4) * 8;

    // Q tile: 128 rows x 64 bf16
#pragma unroll
    for (int i = 0; i < 4; i++) {
        int l = tid + i * 256;
        int row = l >> 3, seg = l & 7;
        cpasync16(smem_u32(Qs + row * TS + seg * 8),
                  base + (size_t)(qt * 128 + row) * NQKV + seg * 8);
    }
    auto load_kv = [&](int kt, int buf) {
#pragma unroll
        for (int i = 0; i < 2; i++) {
            int l = tid + i * 256;
            int row = l >> 3, seg = l & 7;
            const __nv_bfloat16* gp = base + (size_t)(kt * 64 + row) * NQKV + seg * 8;
            cpasync16(smem_u32(Ks + buf * ATTN_KV_ELE + row * TS + seg * 8), gp + HDIM);
            cpasync16(smem_u32(Vs + buf * ATTN_KV_ELE + row * TS + seg * 8), gp + 2 * HDIM);
        }
    };
    load_kv(0, 0);
    CP_COMMIT();

    uint32_t qf[4][4];     // Q A-fragments, preloaded after first wait
    float o[8][4];
#pragma unroll
    for (int ni = 0; ni < 8; ni++)
#pragma unroll
        for (int q = 0; q < 4; q++) o[ni][q] = 0.0f;
    float m_lo = -1e30f, m_hi = -1e30f, l_lo = 0.0f, l_hi = 0.0f;

    for (int kt = 0; kt < 32; kt++) {
        const int buf = kt & 1;
        if (kt + 1 < 32) { load_kv(kt + 1, buf ^ 1); CP_COMMIT(); CP_WAIT1(); }
        else { CP_WAIT0(); }
        __syncthreads();

        if (kt == 0) {
#pragma unroll
            for (int kc = 0; kc < 4; kc++)
                ldmatrix_x4(qf[kc], smem_u32(Qs + (w * 16 + l16) * TS + kc * 16 + lhi));
        }

        // ---- S = Q K^T ----
        const __nv_bfloat16* Kb = Ks + buf * ATTN_KV_ELE;
        float sfr[8][4];
#pragma unroll
        for (int ni = 0; ni < 8; ni++)
#pragma unroll
            for (int q = 0; q < 4; q++) sfr[ni][q] = 0.0f;
#pragma unroll
        for (int kc = 0; kc < 4; kc++) {
#pragma unroll
            for (int p = 0; p < 4; p++) {
                // non-trans ldmatrix: B-frags for n-tiles 2p, 2p+1 at k=kc*16
                uint32_t t4[4];
                uint32_t addr = smem_u32(Kb + (p * 16 + ((lane >> 4) << 3) + (lane & 7)) * TS
                                         + kc * 16 + (((lane >> 3) & 1) << 3));
                ldmatrix_x4(t4, addr);
                mma_bf16(sfr[2 * p],     qf[kc], &t4[0]);
                mma_bf16(sfr[2 * p + 1], qf[kc], &t4[2]);
            }
        }

        // ---- online softmax (register-resident, quad shuffles) ----
        float tl = -1e30f, th = -1e30f;
#pragma unroll
        for (int ni = 0; ni < 8; ni++) {
            tl = fmaxf(tl, fmaxf(sfr[ni][0], sfr[ni][1]));
            th = fmaxf(th, fmaxf(sfr[ni][2], sfr[ni][3]));
        }
        tl = fmaxf(tl, __shfl_xor_sync(0xffffffffu, tl, 1));
        tl = fmaxf(tl, __shfl_xor_sync(0xffffffffu, tl, 2));
        th = fmaxf(th, __shfl_xor_sync(0xffffffffu, th, 1));
        th = fmaxf(th, __shfl_xor_sync(0xffffffffu, th, 2));

        float mnl = fmaxf(m_lo, tl), mnh = fmaxf(m_hi, th);
        float al = __expf(m_lo - mnl), ah = __expf(m_hi - mnh);
        m_lo = mnl; m_hi = mnh;

        float sl = 0.0f, shi = 0.0f;
#pragma unroll
        for (int ni = 0; ni < 8; ni++) {
            sfr[ni][0] = __expf(sfr[ni][0] - m_lo);
            sfr[ni][1] = __expf(sfr[ni][1] - m_lo);
            sfr[ni][2] = __expf(sfr[ni][2] - m_hi);
            sfr[ni][3] = __expf(sfr[ni][3] - m_hi);
            sl  += sfr[ni][0] + sfr[ni][1];
            shi += sfr[ni][2] + sfr[ni][3];
        }
        l_lo = l_lo * al + sl;
        l_hi = l_hi * ah + shi;
#pragma unroll
        for (int ni = 0; ni < 8; ni++) {
            o[ni][0] *= al; o[ni][1] *= al;
            o[ni][2] *= ah; o[ni][3] *= ah;
        }

        // pack P into A-fragments (C-frag of S == A-frag of PV)
        uint32_t pu[4][4];
#pragma unroll
        for (int j = 0; j < 4; j++) {
            pu[j][0] = pack_bf16(sfr[2 * j][0],     sfr[2 * j][1]);
            pu[j][1] = pack_bf16(sfr[2 * j][2],     sfr[2 * j][3]);
            pu[j][2] = pack_bf16(sfr[2 * j + 1][0], sfr[2 * j + 1][1]);
            pu[j][3] = pack_bf16(sfr[2 * j + 1][2], sfr[2 * j + 1][3]);
        }

        // ---- O += P V ----
        const __nv_bfloat16* Vb = Vs + buf * ATTN_KV_ELE;
#pragma unroll
        for (int kc = 0; kc < 4; kc++) {
#pragma unroll
            for (int p = 0; p < 4; p++) {
                uint32_t t4[4];
                ldmatrix_x4t(t4, smem_u32(Vb + (kc * 16 + l16) * TS + p * 16 + lhi));
                mma_bf16(o[2 * p],     pu[kc], &t4[0]);
                mma_bf16(o[2 * p + 1], pu[kc], &t4[2]);
            }
        }
        __syncthreads();
    }

    // final normalize + store bf16 ctx
    l_lo += __shfl_xor_sync(0xffffffffu, l_lo, 1);
    l_lo += __shfl_xor_sync(0xffffffffu, l_lo, 2);
    l_hi += __shfl_xor_sync(0xffffffffu, l_hi, 1);
    l_hi += __shfl_xor_sync(0xffffffffu, l_hi, 2);
    const float il = 1.0f / l_lo, ih = 1.0f / l_hi;

    const int row0 = b * SS + qt * 128 + w * 16 + g;
#pragma unroll
    for (int ni = 0; ni < 8; ni++) {
        const int col = h * HDIM + ni * 8 + 2 * tig;
        *(uint32_t*)(ctx + (size_t)row0 * HH + col) =
            pack_bf16(o[ni][0] * il, o[ni][1] * il);
        *(uint32_t*)(ctx + (size_t)(row0 + 8) * HH + col) =
            pack_bf16(o[ni][2] * ih, o[ni][3] * ih);
    }
}

// ============================================================================
// LayerNorm over H=1024, one block per row.
// ============================================================================
__global__ __launch_bounds__(256)
void layernorm_kernel(const float* __restrict__ x, const float* __restrict__ gamma,
                      const float* __restrict__ beta, float* __restrict__ out)
{
    __shared__ float red[256];
    const int row = blockIdx.x;
    const int tid = threadIdx.x;

    const float4 v = ((const float4*)(x + (size_t)row * HH))[tid];
    float s = v.x + v.y + v.z + v.w;
    red[tid] = s;
    __syncthreads();
#pragma unroll
    for (int o = 128; o > 0; o >>= 1) {
        if (tid < o) red[tid] += red[tid + o];
        __syncthreads();
    }
    const float mu = red[0] * (1.0f / HH);
    __syncthreads();

    const float dx = v.x - mu, dy = v.y - mu, dz = v.z - mu, dw = v.w - mu;
    red[tid] = dx * dx + dy * dy + dz * dz + dw * dw;
    __syncthreads();
#pragma unroll
    for (int o = 128; o > 0; o >>= 1) {
        if (tid < o) red[tid] += red[tid + o];
        __syncthreads();
    }
    const float var = red[0] * (1.0f / HH);
    const float rstd = rsqrtf(var + 1e-5f);

    const float4 gm = ((const float4*)gamma)[tid];
    const float4 bt = ((const float4*)beta)[tid];
    float4 o;
    o.x = dx * rstd * gm.x + bt.x;
    o.y = dy * rstd * gm.y + bt.y;
    o.z = dz * rstd * gm.z + bt.z;
    o.w = dw * rstd * gm.w + bt.w;
    ((float4*)(out + (size_t)row * HH))[tid] = o;
}

// ============================================================================
extern "C" void kernel_launch(void* const* d_in, const int* in_sizes, int n_in,
                              void* d_out, int out_size)
{
    const float* hidden  = (const float*)d_in[0];
    const float* w_qkv   = (const float*)d_in[1];
    const float* b_qkv   = (const float*)d_in[2];
    const float* w_dense = (const float*)d_in[3];
    const float* b_dense = (const float*)d_in[4];
    const float* gamma   = (const float*)d_in[5];
    const float* beta    = (const float*)d_in[6];
    float* out = (float*)d_out;

    __nv_bfloat16 *hid, *wq, *wd, *qkv, *ctx;
    float* x;
    cudaGetSymbolAddress((void**)&hid, g_hid_bf);
    cudaGetSymbolAddress((void**)&wq,  g_wq_bf);
    cudaGetSymbolAddress((void**)&wd,  g_wd_bf);
    cudaGetSymbolAddress((void**)&qkv, g_qkv_bf);
    cudaGetSymbolAddress((void**)&ctx, g_ctx_bf);
    cudaGetSymbolAddress((void**)&x,   g_x);

    // 0) fp32 -> bf16 converts
    f2bf_kernel<<<(MTOT * HH) / 1024, 256>>>(hidden, hid);
    f2bf_kernel<<<(HH * NQKV) / 1024, 256>>>(w_qkv, wq);
    f2bf_kernel<<<(HH * HH) / 1024, 256>>>(w_dense, wd);

    // 1) QKV projection -> bf16 (Q pre-scaled by 1/8)
    cudaFuncSetAttribute(gemm_bf16_kernel<true>,
                         cudaFuncAttributeMaxDynamicSharedMemorySize, GEMM_SMEM_BYTES);
    gemm_bf16_kernel<true><<<dim3(NQKV / 128, MTOT / 128), 256, GEMM_SMEM_BYTES>>>(
        hid, wq, b_qkv, nullptr, qkv, HH, NQKV);

    // 2) Flash attention (bf16 MMA, register softmax)
    cudaFuncSetAttribute(attn_bf16_kernel,
                         cudaFuncAttributeMaxDynamicSharedMemorySize, ATTN_SMEM_BYTES);
    attn_bf16_kernel<<<dim3(32, 16), 256, ATTN_SMEM_BYTES>>>(qkv, ctx);

    // 3) Dense projection + bias + residual -> fp32
    cudaFuncSetAttribute(gemm_bf16_kernel<false>,
                         cudaFuncAttributeMaxDynamicSharedMemorySize, GEMM_SMEM_BYTES);
    gemm_bf16_kernel<false><<<dim3(HH / 128, MTOT / 128), 256, GEMM_SMEM_BYTES>>>(
        ctx, wd, b_dense, hidden, x, HH, HH);

    // 4) LayerNorm
    layernorm_kernel<<<MTOT, 256>>>(x, gamma, beta, out);
}

// round 5
// speedup vs baseline: 6.8542x; 1.0248x over previous
#include <cuda_runtime.h>
#include <cuda_bf16.h>
#include <cstdint>
#include <math.h>

#define BB 2
#define SS 2048
#define HH 1024
#define NHEADS 16
#define HDIM 64
#define MTOT (BB*SS)      // 4096
#define NQKV (3*HH)       // 3072

// Scratch (allocation-free rule: __device__ globals)
__device__ __nv_bfloat16 g_hid_bf[(size_t)MTOT * HH];    // 8 MiB
__device__ __nv_bfloat16 g_wq_bf[(size_t)HH * NQKV];     // 6 MiB
__device__ __nv_bfloat16 g_wd_bf[(size_t)HH * HH];       // 2 MiB
__device__ __nv_bfloat16 g_qkv_bf[(size_t)MTOT * NQKV];  // 24 MiB (Q pre-scaled 1/8)
__device__ __nv_bfloat16 g_ctx_bf[(size_t)MTOT * HH];    // 8 MiB
__device__ float g_x[(size_t)MTOT * HH];                 // 16 MiB

// ============================================================================
// helpers
// ============================================================================
__device__ __forceinline__ uint32_t smem_u32(const void* p) {
    uint32_t a;
    asm("{ .reg .u64 t; cvta.to.shared.u64 t, %1; cvt.u32.u64 %0, t; }"
        : "=r"(a) : "l"(p));
    return a;
}
__device__ __forceinline__ void cpasync16(uint32_t s, const void* g) {
    asm volatile("cp.async.cg.shared.global [%0], [%1], 16;" :: "r"(s), "l"(g));
}
#define CP_COMMIT() asm volatile("cp.async.commit_group;" ::: "memory")
#define CP_WAIT0()  asm volatile("cp.async.wait_group 0;" ::: "memory")
#define CP_WAIT1()  asm volatile("cp.async.wait_group 1;" ::: "memory")
#define CP_WAIT2()  asm volatile("cp.async.wait_group 2;" ::: "memory")

// pack two f32 -> bf16x2 (lo = first arg, hi = second arg)
__device__ __forceinline__ uint32_t pack_bf16(float lo, float hi) {
    uint32_t r;
    asm("cvt.rn.bf16x2.f32 %0, %1, %2;" : "=r"(r) : "f"(hi), "f"(lo));
    return r;
}

// m16n8k16 bf16 MMA, fp32 accumulate
__device__ __forceinline__ void mma_bf16(float c[4], const uint32_t a[4],
                                         const uint32_t b[2]) {
    asm volatile(
        "mma.sync.aligned.m16n8k16.row.col.f32.bf16.bf16.f32 "
        "{%0,%1,%2,%3}, {%4,%5,%6,%7}, {%8,%9}, {%0,%1,%2,%3};\n"
        : "+f"(c[0]), "+f"(c[1]), "+f"(c[2]), "+f"(c[3])
        : "r"(a[0]), "r"(a[1]), "r"(a[2]), "r"(a[3]), "r"(b[0]), "r"(b[1]));
}
__device__ __forceinline__ void ldmatrix_x4(uint32_t r[4], uint32_t addr) {
    asm volatile("ldmatrix.sync.aligned.m8n8.x4.shared.b16 {%0,%1,%2,%3}, [%4];"
                 : "=r"(r[0]), "=r"(r[1]), "=r"(r[2]), "=r"(r[3]) : "r"(addr));
}
__device__ __forceinline__ void ldmatrix_x4t(uint32_t r[4], uint32_t addr) {
    asm volatile("ldmatrix.sync.aligned.m8n8.x4.trans.shared.b16 {%0,%1,%2,%3}, [%4];"
                 : "=r"(r[0]), "=r"(r[1]), "=r"(r[2]), "=r"(r[3]) : "r"(addr));
}

// ============================================================================
// prep: fp32 -> bf16 convert
// ============================================================================
__global__ __launch_bounds__(256)
void f2bf_kernel(const float* __restrict__ in, __nv_bfloat16* __restrict__ out) {
    size_t i = (size_t)blockIdx.x * 256 + threadIdx.x;
    float4 v = ((const float4*)in)[i];
    uint2 o;
    o.x = pack_bf16(v.x, v.y);
    o.y = pack_bf16(v.z, v.w);
    ((uint2*)out)[i] = o;
}

// ============================================================================
// bf16 MMA GEMM: 128x128 CTA tile, BK=64, 256 threads (8 warps, 32x64 warp
// tiles), 3-stage cp.async ring, ONE __syncthreads per stage.
// ============================================================================
#define AS_STR 72
#define BS_STR 136
#define AS_ELE (128 * AS_STR)
#define BS_ELE (64 * BS_STR)
#define STAGE_ELE (AS_ELE + BS_ELE)
#define GEMM_SMEM_BYTES (3 * STAGE_ELE * 2)   // 107520

template<bool QKV>
__global__ __launch_bounds__(256)
void gemm_bf16_kernel(const __nv_bfloat16* __restrict__ A,
                      const __nv_bfloat16* __restrict__ B,
                      const float* __restrict__ bias, const float* __restrict__ res,
                      void* __restrict__ Cout, int K, int N)
{
    extern __shared__ __align__(16) __nv_bfloat16 sh[];

    const int tid = threadIdx.x;
    const int w = tid >> 5, lane = tid & 31;
    const int g = lane >> 2, tig = lane & 3;
    const int wm = w >> 1, wn = w & 1;
    const int bm = blockIdx.y * 128, bn = blockIdx.x * 128;
    const int nst = K / 64;

    float cf[2][8][4];
#pragma unroll
    for (int mi = 0; mi < 2; mi++)
#pragma unroll
        for (int ni = 0; ni < 8; ni++)
#pragma unroll
            for (int q = 0; q < 4; q++) cf[mi][ni][q] = 0.0f;

    auto load_stage = [&](int st, int ks) {
        __nv_bfloat16* As = sh + st * STAGE_ELE;
        __nv_bfloat16* Bs = As + AS_ELE;
#pragma unroll
        for (int i = 0; i < 4; i++) {
            int l = tid + i * 256;
            int row = l >> 3, seg = l & 7;
            cpasync16(smem_u32(As + row * AS_STR + seg * 8),
                      A + (size_t)(bm + row) * K + ks * 64 + seg * 8);
        }
#pragma unroll
        for (int i = 0; i < 4; i++) {
            int l = tid + i * 256;
            int row = l >> 4, seg = l & 15;
            cpasync16(smem_u32(Bs + row * BS_STR + seg * 8),
                      B + (size_t)(ks * 64 + row) * N + bn + seg * 8);
        }
    };

    load_stage(0, 0); CP_COMMIT();
    load_stage(1, 1); CP_COMMIT();
    load_stage(2, 2); CP_COMMIT();

    const int l16 = lane & 15;
    const int lhi = (lane >> 4) * 8;

    for (int ks = 0; ks < nst; ks++) {
        if (ks <= nst - 3)      { CP_WAIT2(); }
        else if (ks == nst - 2) { CP_WAIT1(); }
        else                    { CP_WAIT0(); }
        __syncthreads();

        const int st = ks % 3;
        const __nv_bfloat16* Ab = sh + st * STAGE_ELE;
        const __nv_bfloat16* Bb = Ab + AS_ELE;
#pragma unroll
        for (int kc = 0; kc < 4; kc++) {
            uint32_t au[2][4];
#pragma unroll
            for (int mi = 0; mi < 2; mi++)
                ldmatrix_x4(au[mi], smem_u32(Ab + (wm * 32 + mi * 16 + l16) * AS_STR
                                             + kc * 16 + lhi));
            uint32_t bu[8][2];
#pragma unroll
            for (int p = 0; p < 4; p++) {
                uint32_t t4[4];
                ldmatrix_x4t(t4, smem_u32(Bb + (kc * 16 + l16) * BS_STR
                                          + wn * 64 + p * 16 + lhi));
                bu[2 * p][0] = t4[0]; bu[2 * p][1] = t4[1];
                bu[2 * p + 1][0] = t4[2]; bu[2 * p + 1][1] = t4[3];
            }
#pragma unroll
            for (int mi = 0; mi < 2; mi++)
#pragma unroll
                for (int ni = 0; ni < 8; ni++)
                    mma_bf16(cf[mi][ni], au[mi], bu[ni]);
        }

        if (ks + 3 < nst) { load_stage((ks + 3) % 3, ks + 3); CP_COMMIT(); }
    }

    // epilogue
#pragma unroll
    for (int mi = 0; mi < 2; mi++) {
        const int r = bm + wm * 32 + mi * 16 + g;
#pragma unroll
        for (int ni = 0; ni < 8; ni++) {
            const int c = bn + wn * 64 + ni * 8 + 2 * tig;
            float v0 = cf[mi][ni][0] + bias[c];
            float v1 = cf[mi][ni][1] + bias[c + 1];
            float v2 = cf[mi][ni][2] + bias[c];
            float v3 = cf[mi][ni][3] + bias[c + 1];
            if (QKV) {
                if ((c % 192) < 64) { v0 *= 0.125f; v1 *= 0.125f; v2 *= 0.125f; v3 *= 0.125f; }
                __nv_bfloat16* Cb = (__nv_bfloat16*)Cout;
                *(uint32_t*)(Cb + (size_t)r * N + c) = pack_bf16(v0, v1);
                *(uint32_t*)(Cb + (size_t)(r + 8) * N + c) = pack_bf16(v2, v3);
            } else {
                float* Cf = (float*)Cout;
                const float2 r0 = *(const float2*)(res + (size_t)r * N + c);
                const float2 r1 = *(const float2*)(res + (size_t)(r + 8) * N + c);
                *(float2*)(Cf + (size_t)r * N + c) = make_float2(v0 + r0.x, v1 + r0.y);
                *(float2*)(Cf + (size_t)(r + 8) * N + c) = make_float2(v2 + r1.x, v3 + r1.y);
            }
        }
    }
}

// ============================================================================
// Flash attention, bf16 MMA, register-resident softmax, 4-stage KV ring,
// ONE __syncthreads per k-tile.
// ============================================================================
#define TS 72
#define ATTN_Q_ELE (128 * TS)
#define ATTN_KV_ELE (64 * TS)
#define ATTN_STAGE_ELE (2 * ATTN_KV_ELE)
#define ATTN_SMEM_BYTES ((ATTN_Q_ELE + 4 * ATTN_STAGE_ELE) * 2)  // 92160

__global__ __launch_bounds__(256)
void attn_bf16_kernel(const __nv_bfloat16* __restrict__ qkv,
                      __nv_bfloat16* __restrict__ ctx)
{
    extern __shared__ __align__(16) __nv_bfloat16 sha[];
    __nv_bfloat16* Qs = sha;
    __nv_bfloat16* KV = sha + ATTN_Q_ELE;

    const int bh = blockIdx.x, qt = blockIdx.y;
    const int b = bh >> 4, h = bh & 15;
    const __nv_bfloat16* base = qkv + (size_t)b * SS * NQKV + h * (3 * HDIM);

    const int tid = threadIdx.x;
    const int w = tid >> 5, lane = tid & 31;
    const int g = lane >> 2, tig = lane & 3;
    const int l16 = lane & 15;
    const int lhi = (lane >> 4) * 8;

    auto load_kv = [&](int kt, int st) {
        __nv_bfloat16* Ks = KV + st * ATTN_STAGE_ELE;
        __nv_bfloat16* Vs = Ks + ATTN_KV_ELE;
#pragma unroll
        for (int i = 0; i < 2; i++) {
            int l = tid + i * 256;
            int row = l >> 3, seg = l & 7;
            const __nv_bfloat16* gp = base + (size_t)(kt * 64 + row) * NQKV + seg * 8;
            cpasync16(smem_u32(Ks + row * TS + seg * 8), gp + HDIM);
            cpasync16(smem_u32(Vs + row * TS + seg * 8), gp + 2 * HDIM);
        }
    };

#pragma unroll
    for (int i = 0; i < 4; i++) {
        int l = tid + i * 256;
        int row = l >> 3, seg = l & 7;
        cpasync16(smem_u32(Qs + row * TS + seg * 8),
                  base + (size_t)(qt * 128 + row) * NQKV + seg * 8);
    }
    load_kv(0, 0); CP_COMMIT();
    load_kv(1, 1); CP_COMMIT();
    load_kv(2, 2); CP_COMMIT();

    uint32_t qf[4][4];
    float o[8][4];
#pragma unroll
    for (int ni = 0; ni < 8; ni++)
#pragma unroll
        for (int q = 0; q < 4; q++) o[ni][q] = 0.0f;
    float m_lo = -1e30f, m_hi = -1e30f, l_lo = 0.0f, l_hi = 0.0f;

    for (int kt = 0; kt < 32; kt++) {
        if (kt <= 29)      { CP_WAIT2(); }
        else if (kt == 30) { CP_WAIT1(); }
        else               { CP_WAIT0(); }
        __syncthreads();

        if (kt == 0) {
#pragma unroll
            for (int kc = 0; kc < 4; kc++)
                ldmatrix_x4(qf[kc], smem_u32(Qs + (w * 16 + l16) * TS + kc * 16 + lhi));
        }

        const int st = kt & 3;
        const __nv_bfloat16* Kb = KV + st * ATTN_STAGE_ELE;
        const __nv_bfloat16* Vb = Kb + ATTN_KV_ELE;

        float sfr[8][4];
#pragma unroll
        for (int ni = 0; ni < 8; ni++)
#pragma unroll
            for (int q = 0; q < 4; q++) sfr[ni][q] = 0.0f;
#pragma unroll
        for (int kc = 0; kc < 4; kc++) {
#pragma unroll
            for (int p = 0; p < 4; p++) {
                uint32_t t4[4];
                uint32_t addr = smem_u32(Kb + (p * 16 + ((lane >> 4) << 3) + (lane & 7)) * TS
                                         + kc * 16 + (((lane >> 3) & 1) << 3));
                ldmatrix_x4(t4, addr);
                mma_bf16(sfr[2 * p],     qf[kc], &t4[0]);
                mma_bf16(sfr[2 * p + 1], qf[kc], &t4[2]);
            }
        }

        float tl = -1e30f, th = -1e30f;
#pragma unroll
        for (int ni = 0; ni < 8; ni++) {
            tl = fmaxf(tl, fmaxf(sfr[ni][0], sfr[ni][1]));
            th = fmaxf(th, fmaxf(sfr[ni][2], sfr[ni][3]));
        }
        tl = fmaxf(tl, __shfl_xor_sync(0xffffffffu, tl, 1));
        tl = fmaxf(tl, __shfl_xor_sync(0xffffffffu, tl, 2));
        th = fmaxf(th, __shfl_xor_sync(0xffffffffu, th, 1));
        th = fmaxf(th, __shfl_xor_sync(0xffffffffu, th, 2));

        float mnl = fmaxf(m_lo, tl), mnh = fmaxf(m_hi, th);
        float al = __expf(m_lo - mnl), ah = __expf(m_hi - mnh);
        m_lo = mnl; m_hi = mnh;

        float sl = 0.0f, shi = 0.0f;
#pragma unroll
        for (int ni = 0; ni < 8; ni++) {
            sfr[ni][0] = __expf(sfr[ni][0] - m_lo);
            sfr[ni][1] = __expf(sfr[ni][1] - m_lo);
            sfr[ni][2] = __expf(sfr[ni][2] - m_hi);
            sfr[ni][3] = __expf(sfr[ni][3] - m_hi);
            sl  += sfr[ni][0] + sfr[ni][1];
            shi += sfr[ni][2] + sfr[ni][3];
        }
        l_lo = l_lo * al + sl;
        l_hi = l_hi * ah + shi;
#pragma unroll
        for (int ni = 0; ni < 8; ni++) {
            o[ni][0] *= al; o[ni][1] *= al;
            o[ni][2] *= ah; o[ni][3] *= ah;
        }

        uint32_t pu[4][4];
#pragma unroll
        for (int j = 0; j < 4; j++) {
            pu[j][0] = pack_bf16(sfr[2 * j][0],     sfr[2 * j][1]);
            pu[j][1] = pack_bf16(sfr[2 * j][2],     sfr[2 * j][3]);
            pu[j][2] = pack_bf16(sfr[2 * j + 1][0], sfr[2 * j + 1][1]);
            pu[j][3] = pack_bf16(sfr[2 * j + 1][2], sfr[2 * j + 1][3]);
        }

#pragma unroll
        for (int kc = 0; kc < 4; kc++) {
#pragma unroll
            for (int p = 0; p < 4; p++) {
                uint32_t t4[4];
                ldmatrix_x4t(t4, smem_u32(Vb + (kc * 16 + l16) * TS + p * 16 + lhi));
                mma_bf16(o[2 * p],     pu[kc], &t4[0]);
                mma_bf16(o[2 * p + 1], pu[kc], &t4[2]);
            }
        }

        if (kt + 3 < 32) { load_kv(kt + 3, (kt + 3) & 3); CP_COMMIT(); }
    }

    l_lo += __shfl_xor_sync(0xffffffffu, l_lo, 1);
    l_lo += __shfl_xor_sync(0xffffffffu, l_lo, 2);
    l_hi += __shfl_xor_sync(0xffffffffu, l_hi, 1);
    l_hi += __shfl_xor_sync(0xffffffffu, l_hi, 2);
    const float il = 1.0f / l_lo, ih = 1.0f / l_hi;

    const int row0 = b * SS + qt * 128 + w * 16 + g;
#pragma unroll
    for (int ni = 0; ni < 8; ni++) {
        const int col = h * HDIM + ni * 8 + 2 * tig;
        *(uint32_t*)(ctx + (size_t)row0 * HH + col) =
            pack_bf16(o[ni][0] * il, o[ni][1] * il);
        *(uint32_t*)(ctx + (size_t)(row0 + 8) * HH + col) =
            pack_bf16(o[ni][2] * ih, o[ni][3] * ih);
    }
}

// ============================================================================
// LayerNorm over H=1024, one block per row.
// ============================================================================
__global__ __launch_bounds__(256)
void layernorm_kernel(const float* __restrict__ x, const float* __restrict__ gamma,
                      const float* __restrict__ beta, float* __restrict__ out)
{
    __shared__ float red[256];
    const int row = blockIdx.x;
    const int tid = threadIdx.x;

    const float4 v = ((const float4*)(x + (size_t)row * HH))[tid];
    float s = v.x + v.y + v.z + v.w;
    red[tid] = s;
    __syncthreads();
#pragma unroll
    for (int o = 128; o > 0; o >>= 1) {
        if (tid < o) red[tid] += red[tid + o];
        __syncthreads();
    }
    const float mu = red[0] * (1.0f / HH);
    __syncthreads();

    const float dx = v.x - mu, dy = v.y - mu, dz = v.z - mu, dw = v.w - mu;
    red[tid] = dx * dx + dy * dy + dz * dz + dw * dw;
    __syncthreads();
#pragma unroll
    for (int o = 128; o > 0; o >>= 1) {
        if (tid < o) red[tid] += red[tid + o];
        __syncthreads();
    }
    const float var = red[0] * (1.0f / HH);
    const float rstd = rsqrtf(var + 1e-5f);

    const float4 gm = ((const float4*)gamma)[tid];
    const float4 bt = ((const float4*)beta)[tid];
    float4 o;
    o.x = dx * rstd * gm.x + bt.x;
    o.y = dy * rstd * gm.y + bt.y;
    o.z = dz * rstd * gm.z + bt.z;
    o.w = dw * rstd * gm.w + bt.w;
    ((float4*)(out + (size_t)row * HH))[tid] = o;
}

// ============================================================================
extern "C" void kernel_launch(void* const* d_in, const int* in_sizes, int n_in,
                              void* d_out, int out_size)
{
    const float* hidden  = (const float*)d_in[0];
    const float* w_qkv   = (const float*)d_in[1];
    const float* b_qkv   = (const float*)d_in[2];
    const float* w_dense = (const float*)d_in[3];
    const float* b_dense = (const float*)d_in[4];
    const float* gamma   = (const float*)d_in[5];
    const float* beta    = (const float*)d_in[6];
    float* out = (float*)d_out;

    __nv_bfloat16 *hid, *wq, *wd, *qkv, *ctx;
    float* x;
    cudaGetSymbolAddress((void**)&hid, g_hid_bf);
    cudaGetSymbolAddress((void**)&wq,  g_wq_bf);
    cudaGetSymbolAddress((void**)&wd,  g_wd_bf);
    cudaGetSymbolAddress((void**)&qkv, g_qkv_bf);
    cudaGetSymbolAddress((void**)&ctx, g_ctx_bf);
    cudaGetSymbolAddress((void**)&x,   g_x);

    f2bf_kernel<<<(MTOT * HH) / 1024, 256>>>(hidden, hid);
    f2bf_kernel<<<(HH * NQKV) / 1024, 256>>>(w_qkv, wq);
    f2bf_kernel<<<(HH * HH) / 1024, 256>>>(w_dense, wd);

    cudaFuncSetAttribute(gemm_bf16_kernel<true>,
                         cudaFuncAttributeMaxDynamicSharedMemorySize, GEMM_SMEM_BYTES);
    gemm_bf16_kernel<true><<<dim3(NQKV / 128, MTOT / 128), 256, GEMM_SMEM_BYTES>>>(
        hid, wq, b_qkv, nullptr, qkv, HH, NQKV);

    cudaFuncSetAttribute(attn_bf16_kernel,
                         cudaFuncAttributeMaxDynamicSharedMemorySize, ATTN_SMEM_BYTES);
    attn_bf16_kernel<<<dim3(32, 16), 256, ATTN_SMEM_BYTES>>>(qkv, ctx);

    cudaFuncSetAttribute(gemm_bf16_kernel<false>,
                         cudaFuncAttributeMaxDynamicSharedMemorySize, GEMM_SMEM_BYTES);
    gemm_bf16_kernel<false><<<dim3(HH / 128, MTOT / 128), 256, GEMM_SMEM_BYTES>>>(
        ctx, wd, b_dense, hidden, x, HH, HH);

    layernorm_kernel<<<MTOT, 256>>>(x, gamma, beta, out);
}